// round 5
// baseline (speedup 1.0000x reference)
#include <cuda_runtime.h>
#include <cuda_bf16.h>
#include <cstdint>

// ============================================================================
// SupCon loss, fused, persistent-CTA build.
// se_i = sum_{j!=i} exp(10 d_ij - 10); pd_i = sum_pos d_ij; cf_i = #pos;
// loss_i = -(10 pd - cf (10 + log se)) / (cf + tiny); out = sum_i loss_i.
// 8192 work units (128 rows x 64 cols x K128), dynamic ticket over 444
// persistent CTAs, ticket-indexed partial slots => deterministic output.
// ============================================================================

#define N_TOT   8192
#define D_DIM   128
#define NU      8192          // 64 bi * 128 col-chunks
#define NCHUNK  128
#define PERSIST 444           // 148 SMs * 3 CTAs

__device__ __align__(16) __nv_bfloat16 g_x[N_TOT * D_DIM];
__device__ float g_seb[NCHUNK][N_TOT];
__device__ float g_pdb[NCHUNK][N_TOT];
__device__ float g_cfb[NCHUNK][N_TOT];
__device__ float g_loss[N_TOT];
__device__ int   g_is32;
__device__ int   g_ticket;

// ---------------------------------------------------------------- helpers
__device__ __forceinline__ uint32_t smem_to_u32(const void* p) {
    uint32_t a;
    asm("{ .reg .u64 t; cvta.to.shared.u64 t, %1; cvt.u32.u64 %0, t; }"
        : "=r"(a) : "l"(p));
    return a;
}

__device__ __forceinline__ void ldsm_x4(uint32_t& r0, uint32_t& r1,
                                        uint32_t& r2, uint32_t& r3,
                                        uint32_t addr) {
    asm volatile("ldmatrix.sync.aligned.m8n8.x4.shared.b16 {%0,%1,%2,%3}, [%4];"
                 : "=r"(r0), "=r"(r1), "=r"(r2), "=r"(r3) : "r"(addr));
}

__device__ __forceinline__ void mma_16816(float& c0, float& c1, float& c2, float& c3,
                                          uint32_t a0, uint32_t a1, uint32_t a2, uint32_t a3,
                                          uint32_t b0, uint32_t b1) {
    asm volatile(
        "mma.sync.aligned.m16n8k16.row.col.f32.bf16.bf16.f32 "
        "{%0,%1,%2,%3}, {%4,%5,%6,%7}, {%8,%9}, {%0,%1,%2,%3};"
        : "+f"(c0), "+f"(c1), "+f"(c2), "+f"(c3)
        : "r"(a0), "r"(a1), "r"(a2), "r"(a3), "r"(b0), "r"(b1));
}

__device__ __forceinline__ int getlab(const long long* L64, const int* L32,
                                      int is32, int i) {
    return is32 ? L32[i] : (int)L64[i];
}

// ---------------------------------------------------------------- kernel 0
__global__ void detect_labels(const long long* __restrict__ labels) {
    unsigned hi = (unsigned)(((unsigned long long)labels[threadIdx.x]) >> 32);
    unsigned any = __ballot_sync(0xffffffffu, hi != 0u);
    #pragma unroll
    for (int m = 16; m; m >>= 1) any |= __shfl_xor_sync(0xffffffffu, any, m);
    if (threadIdx.x == 0) { g_is32 = (any != 0u) ? 1 : 0; g_ticket = 0; }
}

// ---------------------------------------------------------------- kernel 1
__global__ void norm_kernel(const float* __restrict__ emb) {
    int row  = blockIdx.x * 8 + (threadIdx.x >> 5);
    int lane = threadIdx.x & 31;
    const float4* e4 = (const float4*)(emb + (size_t)row * D_DIM);
    float4 v = e4[lane];
    float ss = v.x * v.x + v.y * v.y + v.z * v.z + v.w * v.w;
    #pragma unroll
    for (int m = 16; m; m >>= 1) ss += __shfl_xor_sync(0xffffffffu, ss, m);
    float inv = 1.0f / fmaxf(sqrtf(ss), 1e-12f);
    __nv_bfloat162* o = (__nv_bfloat162*)(g_x + (size_t)row * D_DIM);
    o[lane * 2]     = __floats2bfloat162_rn(v.x * inv, v.y * inv);
    o[lane * 2 + 1] = __floats2bfloat162_rn(v.z * inv, v.w * inv);
}

// ---------------------------------------------------------------- kernel 2
// smem: [0,4) ticket, [512,1024) labsh[2][64], [1024,33792) A,
//       [33792,66560) B[2] (16KB each). Tiles swizzled: chunk c at c^(r&7).
__device__ __forceinline__ void epi(float v, int lb, int col, int dcol, int rl,
                                    float& se, float& pd, float& cf) {
    float e = exp2f(fmaf(v, 14.4269504089f, -14.4269504089f));
    if (col != dcol) {
        se += e;
        if (lb == rl) { pd += v; cf += 1.0f; }
    }
}

__global__ void __launch_bounds__(256, 3) supcon_gemm(const long long* __restrict__ lab64) {
    extern __shared__ char smem[];
    int*  s_tick = (int*)smem;
    int*  labsh  = (int*)(smem + 512);
    char* a_ptr  = smem + 1024;
    char* b_ptr  = smem + 33792;
    uint32_t a_sm  = smem_to_u32(a_ptr);
    uint32_t b_sm0 = smem_to_u32(b_ptr);

    const int* lab32 = (const int*)lab64;
    const int is32 = g_is32;

    int tid = threadIdx.x;
    int w   = tid >> 5;
    int l   = tid & 31;
    int qp  = l & 3;
    int r0  = w * 16 + (l >> 2);
    int r1  = r0 + 8;

    int a_row  = w * 16 + ((l >> 3) & 1) * 8 + (l & 7);
    int a_csel = (l >> 4) & 1;
    uint32_t a_base = a_sm + a_row * 256;
    int a_rx = a_row & 7;
    int b_row_off = ((l >> 4) & 1) * 8 + (l & 7);
    int b_csel = (l >> 3) & 1;

    // initial double-pop
    if (tid == 0) *s_tick = atomicAdd(&g_ticket, 2);
    __syncthreads();
    int u = *s_tick;
    int u_next = u + 1;
    if (u >= NU) return;

    int cur_bi = u >> 7;
    // load A tile + row labels
    {
        const uint4* src = (const uint4*)(g_x + (size_t)cur_bi * 128 * D_DIM);
        #pragma unroll
        for (int j = 0; j < 8; j++) {
            int it = tid + j * 256;
            uint4 v = src[it];
            int r = it >> 4, c = it & 15;
            *(uint4*)(a_ptr + r * 256 + ((c ^ (r & 7)) << 4)) = v;
        }
    }
    int rl0 = getlab(lab64, lab32, is32, cur_bi * 128 + r0);
    int rl1 = getlab(lab64, lab32, is32, cur_bi * 128 + r1);
    // load B(u) into buf 0
    {
        int ch = u & 127;
        const uint4* src = (const uint4*)(g_x + (size_t)ch * 64 * D_DIM);
        #pragma unroll
        for (int j = 0; j < 4; j++) {
            int it = tid + j * 256;
            uint4 v = src[it];
            int r = it >> 4, c = it & 15;
            *(uint4*)(b_ptr + r * 256 + ((c ^ (r & 7)) << 4)) = v;
        }
        if (tid < 64) labsh[tid] = getlab(lab64, lab32, is32, ch * 64 + tid);
    }
    __syncthreads();

    int buf = 0;
    while (u < NU) {
        // ---- prefetch next unit's B + labels into registers ----
        bool pf = (u_next < NU);
        uint4 vB0, vB1, vB2, vB3;
        int vL = 0;
        if (pf) {
            int chn = u_next & 127;
            const uint4* src = (const uint4*)(g_x + (size_t)chn * 64 * D_DIM);
            vB0 = src[tid];
            vB1 = src[tid + 256];
            vB2 = src[tid + 512];
            vB3 = src[tid + 768];
            if (tid < 64) vL = getlab(lab64, lab32, is32, chn * 64 + tid);
        }

        // ---- compute current unit ----
        int chunk = u & 127;
        uint32_t b_sm = b_sm0 + buf * 16384;
        const int* labp = labsh + buf * 64;
        int dcol0 = cur_bi * 128 + r0 - chunk * 64;   // local diag col for r0
        int dcol1 = dcol0 + 8;

        float se0 = 0.f, se1 = 0.f, pd0 = 0.f, pd1 = 0.f, cf0 = 0.f, cf1 = 0.f;

        #pragma unroll
        for (int g = 0; g < 4; g++) {
            float c0 = 0.f, c1 = 0.f, c2 = 0.f, c3 = 0.f;
            float d0 = 0.f, d1 = 0.f, d2 = 0.f, d3 = 0.f;
            int brow = g * 16 + b_row_off;
            uint32_t b_base = b_sm + brow * 256;
            int b_rx = brow & 7;
            #pragma unroll
            for (int k = 0; k < 8; k++) {
                uint32_t a0, a1, a2, a3, b0, b1, b2, b3;
                ldsm_x4(a0, a1, a2, a3, a_base + (((2 * k + a_csel) ^ a_rx) << 4));
                ldsm_x4(b0, b1, b2, b3, b_base + (((2 * k + b_csel) ^ b_rx) << 4));
                mma_16816(c0, c1, c2, c3, a0, a1, a2, a3, b0, b1);
                mma_16816(d0, d1, d2, d3, a0, a1, a2, a3, b2, b3);
            }
            int colA = g * 16 + qp * 2;
            int colB = colA + 8;
            int lbA0 = labp[colA],     lbA1 = labp[colA + 1];
            int lbB0 = labp[colB],     lbB1 = labp[colB + 1];
            epi(c0, lbA0, colA,     dcol0, rl0, se0, pd0, cf0);
            epi(c1, lbA1, colA + 1, dcol0, rl0, se0, pd0, cf0);
            epi(c2, lbA0, colA,     dcol1, rl1, se1, pd1, cf1);
            epi(c3, lbA1, colA + 1, dcol1, rl1, se1, pd1, cf1);
            epi(d0, lbB0, colB,     dcol0, rl0, se0, pd0, cf0);
            epi(d1, lbB1, colB + 1, dcol0, rl0, se0, pd0, cf0);
            epi(d2, lbB0, colB,     dcol1, rl1, se1, pd1, cf1);
            epi(d3, lbB1, colB + 1, dcol1, rl1, se1, pd1, cf1);
        }

        // quad reduce + flush to ticket-indexed slot (deterministic)
        #pragma unroll
        for (int off = 1; off <= 2; off <<= 1) {
            se0 += __shfl_xor_sync(0xffffffffu, se0, off);
            se1 += __shfl_xor_sync(0xffffffffu, se1, off);
            pd0 += __shfl_xor_sync(0xffffffffu, pd0, off);
            pd1 += __shfl_xor_sync(0xffffffffu, pd1, off);
            cf0 += __shfl_xor_sync(0xffffffffu, cf0, off);
            cf1 += __shfl_xor_sync(0xffffffffu, cf1, off);
        }
        if (qp == 0) {
            int ig0 = cur_bi * 128 + r0;
            int ig1 = ig0 + 8;
            g_seb[chunk][ig0] = se0; g_pdb[chunk][ig0] = pd0; g_cfb[chunk][ig0] = cf0;
            g_seb[chunk][ig1] = se1; g_pdb[chunk][ig1] = pd1; g_cfb[chunk][ig1] = cf1;
        }

        // ---- pop next-next ticket, store prefetched B ----
        if (tid == 0) *s_tick = atomicAdd(&g_ticket, 1);
        if (pf) {
            char* dst = b_ptr + (buf ^ 1) * 16384;
            int it = tid;
            int r = it >> 4, c = it & 15;
            *(uint4*)(dst + r * 256 + ((c ^ (r & 7)) << 4)) = vB0;
            it += 256; r = it >> 4; c = it & 15;
            *(uint4*)(dst + r * 256 + ((c ^ (r & 7)) << 4)) = vB1;
            it += 256; r = it >> 4; c = it & 15;
            *(uint4*)(dst + r * 256 + ((c ^ (r & 7)) << 4)) = vB2;
            it += 256; r = it >> 4; c = it & 15;
            *(uint4*)(dst + r * 256 + ((c ^ (r & 7)) << 4)) = vB3;
            if (tid < 64) labsh[(buf ^ 1) * 64 + tid] = vL;
        }
        __syncthreads();

        int u2 = *s_tick;
        u = u_next;
        u_next = u2;
        buf ^= 1;

        if (u < NU) {
            int nbi = u >> 7;
            if (nbi != cur_bi) {
                cur_bi = nbi;
                const uint4* src = (const uint4*)(g_x + (size_t)cur_bi * 128 * D_DIM);
                #pragma unroll
                for (int j = 0; j < 8; j++) {
                    int it = tid + j * 256;
                    uint4 v = src[it];
                    int r = it >> 4, c = it & 15;
                    *(uint4*)(a_ptr + r * 256 + ((c ^ (r & 7)) << 4)) = v;
                }
                rl0 = getlab(lab64, lab32, is32, cur_bi * 128 + r0);
                rl1 = getlab(lab64, lab32, is32, cur_bi * 128 + r1);
                __syncthreads();
            }
        }
    }
}

// ---------------------------------------------------------------- kernel 3
__global__ void finalize_rows() {
    int i = blockIdx.x * 256 + threadIdx.x;
    float se = 0.f, pd = 0.f, cf = 0.f;
    #pragma unroll 8
    for (int s = 0; s < NCHUNK; s++) {
        se += g_seb[s][i];
        pd += g_pdb[s][i];
        cf += g_cfb[s][i];
    }
    float lse = 10.0f + logf(se);
    g_loss[i] = -(10.0f * pd - cf * lse) / (cf + 1.17549435e-38f);
}

// ---------------------------------------------------------------- kernel 4
__global__ void reduce_kernel(float* out) {
    __shared__ float sh[256];
    float a = 0.f;
    for (int k = threadIdx.x; k < N_TOT; k += 256) a += g_loss[k];
    sh[threadIdx.x] = a;
    __syncthreads();
    #pragma unroll
    for (int s = 128; s; s >>= 1) {
        if (threadIdx.x < s) sh[threadIdx.x] += sh[threadIdx.x + s];
        __syncthreads();
    }
    if (threadIdx.x == 0) out[0] = sh[0];
}

// ---------------------------------------------------------------- launch
extern "C" void kernel_launch(void* const* d_in, const int* in_sizes, int n_in,
                              void* d_out, int out_size) {
    const float*     emb    = (const float*)d_in[0];
    const long long* labels = (const long long*)d_in[1];

    cudaFuncSetAttribute(supcon_gemm, cudaFuncAttributeMaxDynamicSharedMemorySize, 66560);

    detect_labels<<<1, 64>>>(labels);
    norm_kernel<<<N_TOT / 8, 256>>>(emb);
    supcon_gemm<<<PERSIST, 256, 66560>>>(labels);
    finalize_rows<<<N_TOT / 256, 256>>>();
    reduce_kernel<<<1, 256>>>((float*)d_out);
}

// round 6
// speedup vs baseline: 1.4674x; 1.4674x over previous
#include <cuda_runtime.h>
#include <cuda_bf16.h>
#include <cstdint>

// ============================================================================
// SupCon loss, fused. se_i = sum_j exp(10 d_ij - 10) (diag included, removed
// in finalize); positives (pd_i, cf_i) computed sparsely via label buckets
// (p(pos) ~ 1/1000) so the GEMM epilogue is just exp+add.
// loss_i = -(10 pd - cf (10 + log se)) / (cf + tiny); out = sum_i loss_i.
// ============================================================================

#define N_TOT   8192
#define D_DIM   128
#define NBLK    64
#define SPLITS  8
#define TILES_PER 8
#define KEXP    14.426950408889634f   /* 10*log2(e) */

__device__ __align__(16) __nv_bfloat16 g_x[N_TOT * D_DIM];
__device__ float g_seb[SPLITS][N_TOT];
__device__ float g_loss[N_TOT];
__device__ int   g_is32;
__device__ int   g_part[32][1024];    // per-CTA per-label counts -> offsets
__device__ int   g_start[1025];       // bucket starts (exclusive scan)
__device__ int   g_items[N_TOT];      // row ids grouped by label, ordered

// ---------------------------------------------------------------- helpers
__device__ __forceinline__ uint32_t smem_to_u32(const void* p) {
    uint32_t a;
    asm("{ .reg .u64 t; cvta.to.shared.u64 t, %1; cvt.u32.u64 %0, t; }"
        : "=r"(a) : "l"(p));
    return a;
}
__device__ __forceinline__ void ldsm_x4(uint32_t& r0, uint32_t& r1,
                                        uint32_t& r2, uint32_t& r3,
                                        uint32_t addr) {
    asm volatile("ldmatrix.sync.aligned.m8n8.x4.shared.b16 {%0,%1,%2,%3}, [%4];"
                 : "=r"(r0), "=r"(r1), "=r"(r2), "=r"(r3) : "r"(addr));
}
__device__ __forceinline__ void mma_16816(float& c0, float& c1, float& c2, float& c3,
                                          uint32_t a0, uint32_t a1, uint32_t a2, uint32_t a3,
                                          uint32_t b0, uint32_t b1) {
    asm volatile(
        "mma.sync.aligned.m16n8k16.row.col.f32.bf16.bf16.f32 "
        "{%0,%1,%2,%3}, {%4,%5,%6,%7}, {%8,%9}, {%0,%1,%2,%3};"
        : "+f"(c0), "+f"(c1), "+f"(c2), "+f"(c3)
        : "r"(a0), "r"(a1), "r"(a2), "r"(a3), "r"(b0), "r"(b1));
}
__device__ __forceinline__ int getlab(const long long* L64, int is32, int i) {
    return is32 ? ((const int*)L64)[i] : (int)L64[i];
}
#define CP_ASYNC16(dst, src) \
    asm volatile("cp.async.cg.shared.global [%0], [%1], 16;" \
                 :: "r"(dst), "l"(src) : "memory")
#define CP_COMMIT() asm volatile("cp.async.commit_group;" ::: "memory")
#define CP_WAIT0()  asm volatile("cp.async.wait_group 0;" ::: "memory")

// ---------------------------------------------------------------- kernel 0
__global__ void detect_labels(const long long* __restrict__ labels) {
    unsigned hi = (unsigned)(((unsigned long long)labels[threadIdx.x]) >> 32);
    unsigned any = __ballot_sync(0xffffffffu, hi != 0u);
    #pragma unroll
    for (int m = 16; m; m >>= 1) any |= __shfl_xor_sync(0xffffffffu, any, m);
    if (threadIdx.x == 0) g_is32 = (any != 0u) ? 1 : 0;
}

// ---------------------------------------------------------------- kernel 1
__global__ void norm_kernel(const float* __restrict__ emb) {
    int row  = blockIdx.x * 8 + (threadIdx.x >> 5);
    int lane = threadIdx.x & 31;
    const float4* e4 = (const float4*)(emb + (size_t)row * D_DIM);
    float4 v = e4[lane];
    float ss = v.x * v.x + v.y * v.y + v.z * v.z + v.w * v.w;
    #pragma unroll
    for (int m = 16; m; m >>= 1) ss += __shfl_xor_sync(0xffffffffu, ss, m);
    float inv = 1.0f / fmaxf(sqrtf(ss), 1e-12f);
    __nv_bfloat162* o = (__nv_bfloat162*)(g_x + (size_t)row * D_DIM);
    o[lane * 2]     = __floats2bfloat162_rn(v.x * inv, v.y * inv);
    o[lane * 2 + 1] = __floats2bfloat162_rn(v.z * inv, v.w * inv);
}

// ---------------------------------------------------------------- bucket build
__global__ void hist1(const long long* __restrict__ lab64) {
    __shared__ int cnt[1024];
    int tid = threadIdx.x, blk = blockIdx.x;
    #pragma unroll
    for (int j = 0; j < 4; j++) cnt[tid + j * 256] = 0;
    __syncthreads();
    int lab = getlab(lab64, g_is32, blk * 256 + tid);
    atomicAdd(&cnt[lab], 1);
    __syncthreads();
    #pragma unroll
    for (int j = 0; j < 4; j++) g_part[blk][tid + j * 256] = cnt[tid + j * 256];
}

__global__ void hist2() {
    __shared__ int s[2][1024];
    int tid = threadIdx.x;
    int run = 0;
    #pragma unroll 4
    for (int c = 0; c < 32; c++) {
        int t = g_part[c][tid];
        g_part[c][tid] = run;        // intra-label prefix over CTAs
        run += t;
    }
    s[0][tid] = run;                 // total count per label
    __syncthreads();
    int p = 0;
    #pragma unroll
    for (int off = 1; off < 1024; off <<= 1) {
        int v = s[p][tid];
        if (tid >= off) v += s[p][tid - off];
        s[p ^ 1][tid] = v;
        p ^= 1;
        __syncthreads();
    }
    int incl = s[p][tid];
    int excl = incl - run;
    g_start[tid] = excl;
    if (tid == 0) g_start[1024] = N_TOT;
    __syncthreads();
    #pragma unroll 4
    for (int c = 0; c < 32; c++) g_part[c][tid] += excl;
}

__global__ void hist3(const long long* __restrict__ lab64) {
    __shared__ int slab[256];
    int tid = threadIdx.x, blk = blockIdx.x;
    int row = blk * 256 + tid;
    int lab = getlab(lab64, g_is32, row);
    slab[tid] = lab;
    __syncthreads();
    int rank = 0;
    for (int j = 0; j < tid; j++) rank += (slab[j] == lab);
    g_items[g_part[blk][lab] + rank] = row;
}

// ---------------------------------------------------------------- kernel 2:
// GEMM + exp-sum epilogue. grid (64 bi, 8 sp), 256 thr, cp.async dbl-buf B.
__global__ void __launch_bounds__(256, 2) supcon_gemm() {
    extern __shared__ char smem[];
    char* a_ptr  = smem;                 // 32 KB
    char* b_ptr  = smem + 32768;         // 2 x 32 KB
    uint32_t a_sm  = smem_to_u32(a_ptr);
    uint32_t b_sm0 = smem_to_u32(b_ptr);

    int tid = threadIdx.x;
    int w   = tid >> 5;
    int l   = tid & 31;
    int qp  = l & 3;
    int r0  = w * 16 + (l >> 2);

    // async-load A tile (swizzled: 16B chunk c of row r -> c^(r&7))
    {
        const char* src = (const char*)g_x + (size_t)blockIdx.x * 32768;
        #pragma unroll
        for (int j = 0; j < 8; j++) {
            int it = tid + j * 256;
            int r = it >> 4, c = it & 15;
            CP_ASYNC16(a_sm + r * 256 + ((c ^ (r & 7)) << 4),
                       src + (size_t)it * 16);
        }
    }
    // async-load first B tile into buf 0
    {
        const char* src = (const char*)g_x + (size_t)(blockIdx.y * 8) * 32768;
        #pragma unroll
        for (int j = 0; j < 8; j++) {
            int it = tid + j * 256;
            int r = it >> 4, c = it & 15;
            CP_ASYNC16(b_sm0 + r * 256 + ((c ^ (r & 7)) << 4),
                       src + (size_t)it * 16);
        }
    }
    CP_COMMIT();

    int a_row  = w * 16 + ((l >> 3) & 1) * 8 + (l & 7);
    int a_csel = (l >> 4) & 1;
    uint32_t a_base = a_sm + a_row * 256;
    int a_rx = a_row & 7;
    int b_row_off = ((l >> 4) & 1) * 8 + (l & 7);
    int b_csel = (l >> 3) & 1;

    float sea = 0.f, seb = 0.f, sec = 0.f, sed = 0.f;

    for (int t = 0; t < TILES_PER; t++) {
        CP_WAIT0();
        __syncthreads();

        if (t < 7) {   // prefetch next B into other buffer
            const char* src = (const char*)g_x
                            + (size_t)(blockIdx.y * 8 + t + 1) * 32768;
            uint32_t dstb = b_sm0 + ((t + 1) & 1) * 32768;
            #pragma unroll
            for (int j = 0; j < 8; j++) {
                int it = tid + j * 256;
                int r = it >> 4, c = it & 15;
                CP_ASYNC16(dstb + r * 256 + ((c ^ (r & 7)) << 4),
                           src + (size_t)it * 16);
            }
            CP_COMMIT();
        }

        uint32_t b_sm = b_sm0 + (t & 1) * 32768;
        float acc[16][4];
        #pragma unroll
        for (int f = 0; f < 16; f++)
            #pragma unroll
            for (int e = 0; e < 4; e++) acc[f][e] = 0.f;

        #pragma unroll
        for (int k = 0; k < 8; k++) {
            uint32_t a0, a1, a2, a3;
            ldsm_x4(a0, a1, a2, a3, a_base + (((2 * k + a_csel) ^ a_rx) << 4));
            #pragma unroll
            for (int n2 = 0; n2 < 8; n2++) {
                int brow = n2 * 16 + b_row_off;
                uint32_t b0, b1, b2, b3;
                ldsm_x4(b0, b1, b2, b3,
                        b_sm + brow * 256 + (((2 * k + b_csel) ^ (brow & 7)) << 4));
                mma_16816(acc[2*n2][0],   acc[2*n2][1],   acc[2*n2][2],   acc[2*n2][3],
                          a0, a1, a2, a3, b0, b1);
                mma_16816(acc[2*n2+1][0], acc[2*n2+1][1], acc[2*n2+1][2], acc[2*n2+1][3],
                          a0, a1, a2, a3, b2, b3);
            }
        }

        // epilogue: pure exp-sum (diag included; positives handled elsewhere)
        #pragma unroll
        for (int f = 0; f < 16; f++) {
            sea += exp2f(fmaf(acc[f][0], KEXP, -KEXP));
            seb += exp2f(fmaf(acc[f][1], KEXP, -KEXP));
            sec += exp2f(fmaf(acc[f][2], KEXP, -KEXP));
            sed += exp2f(fmaf(acc[f][3], KEXP, -KEXP));
        }
    }

    float se0 = sea + seb;   // row r0
    float se1 = sec + sed;   // row r0 + 8
    #pragma unroll
    for (int off = 1; off <= 2; off <<= 1) {
        se0 += __shfl_xor_sync(0xffffffffu, se0, off);
        se1 += __shfl_xor_sync(0xffffffffu, se1, off);
    }
    if (qp == 0) {
        int ig = blockIdx.x * 128 + r0;
        g_seb[blockIdx.y][ig]     = se0;
        g_seb[blockIdx.y][ig + 8] = se1;
    }
}

// ---------------------------------------------------------------- kernel 3:
// warp per row: pd/cf from bucket, d_ii, assemble loss.
__global__ void finalize_rows(const long long* __restrict__ lab64) {
    int wgl  = (blockIdx.x * blockDim.x + threadIdx.x) >> 5;   // row id
    int l    = threadIdx.x & 31;
    int i    = wgl;

    // own row (4 bf16 per lane)
    const uint2* xr = (const uint2*)(g_x + (size_t)i * D_DIM);
    uint2 xv = xr[l];
    __nv_bfloat162 p0 = *(__nv_bfloat162*)&xv.x;
    __nv_bfloat162 p1 = *(__nv_bfloat162*)&xv.y;
    float x0 = __bfloat162float(p0.x), x1 = __bfloat162float(p0.y);
    float x2 = __bfloat162float(p1.x), x3 = __bfloat162float(p1.y);

    float dii = x0 * x0 + x1 * x1 + x2 * x2 + x3 * x3;
    #pragma unroll
    for (int m = 16; m; m >>= 1) dii += __shfl_xor_sync(0xffffffffu, dii, m);

    float se = (l < SPLITS) ? g_seb[l][i] : 0.f;
    #pragma unroll
    for (int m = 16; m; m >>= 1) se += __shfl_xor_sync(0xffffffffu, se, m);
    se -= exp2f(fmaf(dii, KEXP, -KEXP));       // remove diagonal

    int lab = getlab(lab64, g_is32, i);
    int s = g_start[lab], e = g_start[lab + 1];
    float pd = 0.f;
    for (int m = s; m < e; m++) {
        int j = g_items[m];
        if (j == i) continue;
        uint2 yv = ((const uint2*)(g_x + (size_t)j * D_DIM))[l];
        __nv_bfloat162 q0 = *(__nv_bfloat162*)&yv.x;
        __nv_bfloat162 q1 = *(__nv_bfloat162*)&yv.y;
        float d = x0 * __bfloat162float(q0.x) + x1 * __bfloat162float(q0.y)
                + x2 * __bfloat162float(q1.x) + x3 * __bfloat162float(q1.y);
        #pragma unroll
        for (int m2 = 16; m2; m2 >>= 1) d += __shfl_xor_sync(0xffffffffu, d, m2);
        pd += d;
    }
    if (l == 0) {
        float cf  = (float)(e - s - 1);
        float lse = 10.0f + logf(se);
        g_loss[i] = -(10.0f * pd - cf * lse) / (cf + 1.17549435e-38f);
    }
}

// ---------------------------------------------------------------- kernel 4
__global__ void reduce_kernel(float* out) {
    __shared__ float sh[256];
    float a = 0.f;
    for (int k = threadIdx.x; k < N_TOT; k += 256) a += g_loss[k];
    sh[threadIdx.x] = a;
    __syncthreads();
    #pragma unroll
    for (int s = 128; s; s >>= 1) {
        if (threadIdx.x < s) sh[threadIdx.x] += sh[threadIdx.x + s];
        __syncthreads();
    }
    if (threadIdx.x == 0) out[0] = sh[0];
}

// ---------------------------------------------------------------- launch
extern "C" void kernel_launch(void* const* d_in, const int* in_sizes, int n_in,
                              void* d_out, int out_size) {
    const float*     emb    = (const float*)d_in[0];
    const long long* labels = (const long long*)d_in[1];

    cudaFuncSetAttribute(supcon_gemm, cudaFuncAttributeMaxDynamicSharedMemorySize, 98304);

    detect_labels<<<1, 64>>>(labels);
    norm_kernel<<<N_TOT / 8, 256>>>(emb);
    hist1<<<32, 256>>>(labels);
    hist2<<<1, 1024>>>();
    hist3<<<32, 256>>>(labels);
    supcon_gemm<<<dim3(NBLK, SPLITS), 256, 98304>>>();
    finalize_rows<<<N_TOT / 8, 256>>>(labels);
    reduce_kernel<<<1, 256>>>((float*)d_out);
}

// round 7
// speedup vs baseline: 1.5832x; 1.0789x over previous
#include <cuda_runtime.h>
#include <cuda_bf16.h>
#include <cstdint>

// ============================================================================
// SupCon loss, fused. se_i = sum_j exp(10 d_ij - 10) (diag incl., removed in
// finalize); positives via deterministic label buckets (p ~ 1/1000).
// loss_i = -(10 pd - cf (10 + log se)) / (cf + tiny); out = sum_i loss_i.
// GEMM: mma.sync bf16, 128x128 CTA tile, 4x2 warp grid (32r x 64c / warp),
// cp.async double-buffered B. Label dtype self-detected (int32 vs int64).
// ============================================================================

#define N_TOT   8192
#define D_DIM   128
#define NBLK    64
#define SPLITS  8            /* B-column splits (grid.y) */
#define SOUT    16           /* se partial slots = SPLITS * 2 warp-cols */
#define TILES_PER 8
#define KEXP    14.426950408889634f   /* 10*log2(e) */

__device__ __align__(16) __nv_bfloat16 g_x[N_TOT * D_DIM];
__device__ float g_seb[SOUT][N_TOT];
__device__ float g_loss[N_TOT];
__device__ int   g_is32;
__device__ int   g_part[32][1024];
__device__ int   g_start[1025];
__device__ int   g_items[N_TOT];

// ---------------------------------------------------------------- helpers
__device__ __forceinline__ uint32_t smem_to_u32(const void* p) {
    uint32_t a;
    asm("{ .reg .u64 t; cvta.to.shared.u64 t, %1; cvt.u32.u64 %0, t; }"
        : "=r"(a) : "l"(p));
    return a;
}
__device__ __forceinline__ void ldsm_x4(uint32_t& r0, uint32_t& r1,
                                        uint32_t& r2, uint32_t& r3,
                                        uint32_t addr) {
    asm volatile("ldmatrix.sync.aligned.m8n8.x4.shared.b16 {%0,%1,%2,%3}, [%4];"
                 : "=r"(r0), "=r"(r1), "=r"(r2), "=r"(r3) : "r"(addr));
}
__device__ __forceinline__ void mma_16816(float& c0, float& c1, float& c2, float& c3,
                                          uint32_t a0, uint32_t a1, uint32_t a2, uint32_t a3,
                                          uint32_t b0, uint32_t b1) {
    asm volatile(
        "mma.sync.aligned.m16n8k16.row.col.f32.bf16.bf16.f32 "
        "{%0,%1,%2,%3}, {%4,%5,%6,%7}, {%8,%9}, {%0,%1,%2,%3};"
        : "+f"(c0), "+f"(c1), "+f"(c2), "+f"(c3)
        : "r"(a0), "r"(a1), "r"(a2), "r"(a3), "r"(b0), "r"(b1));
}
__device__ __forceinline__ int getlab(const long long* L64, int is32, int i) {
    return is32 ? ((const int*)L64)[i] : (int)L64[i];
}
#define CP_ASYNC16(dst, src) \
    asm volatile("cp.async.cg.shared.global [%0], [%1], 16;" \
                 :: "r"(dst), "l"(src) : "memory")
#define CP_COMMIT() asm volatile("cp.async.commit_group;" ::: "memory")
#define CP_WAIT0()  asm volatile("cp.async.wait_group 0;" ::: "memory")

// ---------------------------------------------------------------- kernel 1
__global__ void norm_kernel(const float* __restrict__ emb) {
    int row  = blockIdx.x * 8 + (threadIdx.x >> 5);
    int lane = threadIdx.x & 31;
    const float4* e4 = (const float4*)(emb + (size_t)row * D_DIM);
    float4 v = e4[lane];
    float ss = v.x * v.x + v.y * v.y + v.z * v.z + v.w * v.w;
    #pragma unroll
    for (int m = 16; m; m >>= 1) ss += __shfl_xor_sync(0xffffffffu, ss, m);
    float inv = 1.0f / fmaxf(sqrtf(ss), 1e-12f);
    __nv_bfloat162* o = (__nv_bfloat162*)(g_x + (size_t)row * D_DIM);
    o[lane * 2]     = __floats2bfloat162_rn(v.x * inv, v.y * inv);
    o[lane * 2 + 1] = __floats2bfloat162_rn(v.z * inv, v.w * inv);
}

// ---------------------------------------------------------------- bucket build
// hist1: per-CTA label histogram; self-detects label dtype from raw words.
__global__ void hist1(const long long* __restrict__ lab64) {
    __shared__ int cnt[1024];
    __shared__ int s_is32;
    int tid = threadIdx.x, blk = blockIdx.x;
    if (tid == 0) s_is32 = 0;
    #pragma unroll
    for (int j = 0; j < 4; j++) cnt[tid + j * 256] = 0;
    __syncthreads();
    if (tid < 64) {
        unsigned hi = (unsigned)(((unsigned long long)lab64[tid]) >> 32);
        if (hi != 0u) atomicOr(&s_is32, 1);
    }
    __syncthreads();
    int is32 = s_is32;
    if (tid == 0 && blk == 0) g_is32 = is32;
    int lab = getlab(lab64, is32, blk * 256 + tid);
    atomicAdd(&cnt[lab], 1);
    __syncthreads();
    #pragma unroll
    for (int j = 0; j < 4; j++) g_part[blk][tid + j * 256] = cnt[tid + j * 256];
}

// hist2: exclusive scan over 1024 label totals (warp-shuffle scan) + fold
// bucket starts into per-CTA bases.
__global__ void hist2() {
    __shared__ int wsum[32];
    int tid = threadIdx.x;          // 1024
    int l = tid & 31, w = tid >> 5;
    int pref[32];
    int run = 0;
    #pragma unroll
    for (int c = 0; c < 32; c++) {
        int t = g_part[c][tid];
        pref[c] = run;
        run += t;
    }
    // inclusive warp scan of per-label totals
    int x = run;
    #pragma unroll
    for (int o = 1; o < 32; o <<= 1) {
        int v = __shfl_up_sync(0xffffffffu, x, o);
        if (l >= o) x += v;
    }
    if (l == 31) wsum[w] = x;
    __syncthreads();
    if (tid < 32) {
        int y = wsum[tid];
        #pragma unroll
        for (int o = 1; o < 32; o <<= 1) {
            int v = __shfl_up_sync(0xffffffffu, y, o);
            if (tid >= o) y += v;
        }
        wsum[tid] = y;
    }
    __syncthreads();
    int incl = x + (w ? wsum[w - 1] : 0);
    int excl = incl - run;
    g_start[tid] = excl;
    if (tid == 0) g_start[1024] = N_TOT;
    #pragma unroll
    for (int c = 0; c < 32; c++) g_part[c][tid] = pref[c] + excl;
}

// hist3: deterministic rank-ordered scatter of row ids into buckets.
__global__ void hist3(const long long* __restrict__ lab64) {
    __shared__ int slab[256];
    int tid = threadIdx.x, blk = blockIdx.x;
    int row = blk * 256 + tid;
    int lab = getlab(lab64, g_is32, row);
    slab[tid] = lab;
    __syncthreads();
    int rank = 0;
    for (int j = 0; j < tid; j++) rank += (slab[j] == lab);
    g_items[g_part[blk][lab] + rank] = row;
}

// ---------------------------------------------------------------- kernel 2:
// GEMM + exp-sum epilogue. grid (64 bi, 8 sp), 256 thr (4x2 warp grid).
__global__ void __launch_bounds__(256, 2) supcon_gemm() {
    extern __shared__ char smem[];
    uint32_t a_sm  = smem_to_u32(smem);
    uint32_t b_sm0 = a_sm + 32768;

    int tid = threadIdx.x;
    int w   = tid >> 5;
    int l   = tid & 31;
    int wy  = w >> 1;          // 0..3  -> rows 32*wy..+31
    int wx  = w & 1;           // 0..1  -> cols 64*wx..+63
    int qp  = l & 3;

    // async-load A tile (swizzle: 16B chunk c of row r -> c^(r&7))
    {
        const char* src = (const char*)g_x + (size_t)blockIdx.x * 32768;
        #pragma unroll
        for (int j = 0; j < 8; j++) {
            int it = tid + j * 256;
            int r = it >> 4, c = it & 15;
            CP_ASYNC16(a_sm + r * 256 + ((c ^ (r & 7)) << 4),
                       src + (size_t)it * 16);
        }
    }
    {
        const char* src = (const char*)g_x + (size_t)(blockIdx.y * 8) * 32768;
        #pragma unroll
        for (int j = 0; j < 8; j++) {
            int it = tid + j * 256;
            int r = it >> 4, c = it & 15;
            CP_ASYNC16(b_sm0 + r * 256 + ((c ^ (r & 7)) << 4),
                       src + (size_t)it * 16);
        }
    }
    CP_COMMIT();

    // ldsm lane geometry
    int a_row  = 32 * wy + ((l >> 3) & 1) * 8 + (l & 7);   // + 16*mrow
    int a_csel = (l >> 4) & 1;
    int a_rx   = a_row & 7;
    uint32_t a_base0 = a_sm + a_row * 256;                 // mrow0; +4096 for mrow1
    int b_row  = 64 * wx + ((l >> 4) & 1) * 8 + (l & 7);   // + 16*g
    int b_csel = (l >> 3) & 1;
    int b_rx   = b_row & 7;

    float se[4] = {0.f, 0.f, 0.f, 0.f};    // [mrow*2 + h]

    for (int t = 0; t < TILES_PER; t++) {
        CP_WAIT0();
        __syncthreads();

        if (t < 7) {
            const char* src = (const char*)g_x
                            + (size_t)(blockIdx.y * 8 + t + 1) * 32768;
            uint32_t dstb = b_sm0 + ((t + 1) & 1) * 32768;
            #pragma unroll
            for (int j = 0; j < 8; j++) {
                int it = tid + j * 256;
                int r = it >> 4, c = it & 15;
                CP_ASYNC16(dstb + r * 256 + ((c ^ (r & 7)) << 4),
                           src + (size_t)it * 16);
            }
            CP_COMMIT();
        }

        uint32_t b_smt = b_sm0 + (t & 1) * 32768;
        uint32_t b_base0 = b_smt + b_row * 256;

        float acc[2][8][4];
        #pragma unroll
        for (int m = 0; m < 2; m++)
            #pragma unroll
            for (int n = 0; n < 8; n++)
                #pragma unroll
                for (int e = 0; e < 4; e++) acc[m][n][e] = 0.f;

        #pragma unroll
        for (int k = 0; k < 8; k++) {
            uint32_t ka = (uint32_t)(((2 * k + a_csel) ^ a_rx) << 4);
            uint32_t kb = (uint32_t)(((2 * k + b_csel) ^ b_rx) << 4);
            uint32_t a0[4], a1[4];
            ldsm_x4(a0[0], a0[1], a0[2], a0[3], a_base0 + ka);
            ldsm_x4(a1[0], a1[1], a1[2], a1[3], a_base0 + 4096 + ka);
            #pragma unroll
            for (int g = 0; g < 4; g++) {
                uint32_t b0, b1, b2, b3;
                ldsm_x4(b0, b1, b2, b3, b_base0 + g * 4096 + kb);
                mma_16816(acc[0][2*g][0],   acc[0][2*g][1],   acc[0][2*g][2],   acc[0][2*g][3],
                          a0[0], a0[1], a0[2], a0[3], b0, b1);
                mma_16816(acc[0][2*g+1][0], acc[0][2*g+1][1], acc[0][2*g+1][2], acc[0][2*g+1][3],
                          a0[0], a0[1], a0[2], a0[3], b2, b3);
                mma_16816(acc[1][2*g][0],   acc[1][2*g][1],   acc[1][2*g][2],   acc[1][2*g][3],
                          a1[0], a1[1], a1[2], a1[3], b0, b1);
                mma_16816(acc[1][2*g+1][0], acc[1][2*g+1][1], acc[1][2*g+1][2], acc[1][2*g+1][3],
                          a1[0], a1[1], a1[2], a1[3], b2, b3);
            }
        }

        // epilogue: pure exp-sum (diag incl., positives handled elsewhere)
        #pragma unroll
        for (int m = 0; m < 2; m++)
            #pragma unroll
            for (int n = 0; n < 8; n++) {
                se[m*2+0] += exp2f(fmaf(acc[m][n][0], KEXP, -KEXP))
                           + exp2f(fmaf(acc[m][n][1], KEXP, -KEXP));
                se[m*2+1] += exp2f(fmaf(acc[m][n][2], KEXP, -KEXP))
                           + exp2f(fmaf(acc[m][n][3], KEXP, -KEXP));
            }
    }

    #pragma unroll
    for (int v = 0; v < 4; v++) {
        #pragma unroll
        for (int off = 1; off <= 2; off <<= 1)
            se[v] += __shfl_xor_sync(0xffffffffu, se[v], off);
    }
    if (qp == 0) {
        int q = l >> 2;
        int slot = blockIdx.y * 2 + wx;
        #pragma unroll
        for (int m = 0; m < 2; m++)
            #pragma unroll
            for (int h = 0; h < 2; h++) {
                int row_l = 32 * wy + 16 * m + 8 * h + q;
                g_seb[slot][blockIdx.x * 128 + row_l] = se[m*2+h];
            }
    }
}

// ---------------------------------------------------------------- kernel 3:
// warp per row: se assemble, d_ii, sparse pd/cf from bucket.
__global__ void finalize_rows(const long long* __restrict__ lab64) {
    int i = (blockIdx.x * blockDim.x + threadIdx.x) >> 5;
    int l = threadIdx.x & 31;

    const uint2* xr = (const uint2*)(g_x + (size_t)i * D_DIM);
    uint2 xv = xr[l];
    __nv_bfloat162 p0 = *(__nv_bfloat162*)&xv.x;
    __nv_bfloat162 p1 = *(__nv_bfloat162*)&xv.y;
    float x0 = __bfloat162float(p0.x), x1 = __bfloat162float(p0.y);
    float x2 = __bfloat162float(p1.x), x3 = __bfloat162float(p1.y);

    float dii = x0 * x0 + x1 * x1 + x2 * x2 + x3 * x3;
    #pragma unroll
    for (int m = 16; m; m >>= 1) dii += __shfl_xor_sync(0xffffffffu, dii, m);

    float se = (l < SOUT) ? g_seb[l][i] : 0.f;
    #pragma unroll
    for (int m = 16; m; m >>= 1) se += __shfl_xor_sync(0xffffffffu, se, m);
    se -= exp2f(fmaf(dii, KEXP, -KEXP));

    int lab = getlab(lab64, g_is32, i);
    int s = g_start[lab], e = g_start[lab + 1];
    float pd = 0.f;
    for (int m = s; m < e; m++) {
        int j = g_items[m];
        if (j == i) continue;
        uint2 yv = ((const uint2*)(g_x + (size_t)j * D_DIM))[l];
        __nv_bfloat162 q0 = *(__nv_bfloat162*)&yv.x;
        __nv_bfloat162 q1 = *(__nv_bfloat162*)&yv.y;
        float d = x0 * __bfloat162float(q0.x) + x1 * __bfloat162float(q0.y)
                + x2 * __bfloat162float(q1.x) + x3 * __bfloat162float(q1.y);
        #pragma unroll
        for (int m2 = 16; m2; m2 >>= 1) d += __shfl_xor_sync(0xffffffffu, d, m2);
        pd += d;
    }
    if (l == 0) {
        float cf  = (float)(e - s - 1);
        float lse = 10.0f + logf(se);
        g_loss[i] = -(10.0f * pd - cf * lse) / (cf + 1.17549435e-38f);
    }
}

// ---------------------------------------------------------------- kernel 4
__global__ void reduce_kernel(float* out) {
    __shared__ float sh[256];
    float a = 0.f;
    for (int k = threadIdx.x; k < N_TOT; k += 256) a += g_loss[k];
    sh[threadIdx.x] = a;
    __syncthreads();
    #pragma unroll
    for (int s = 128; s; s >>= 1) {
        if (threadIdx.x < s) sh[threadIdx.x] += sh[threadIdx.x + s];
        __syncthreads();
    }
    if (threadIdx.x == 0) out[0] = sh[0];
}

// ---------------------------------------------------------------- launch
extern "C" void kernel_launch(void* const* d_in, const int* in_sizes, int n_in,
                              void* d_out, int out_size) {
    const float*     emb    = (const float*)d_in[0];
    const long long* labels = (const long long*)d_in[1];

    cudaFuncSetAttribute(supcon_gemm, cudaFuncAttributeMaxDynamicSharedMemorySize, 98304);

    norm_kernel<<<N_TOT / 8, 256>>>(emb);
    hist1<<<32, 256>>>(labels);
    hist2<<<1, 1024>>>();
    hist3<<<32, 256>>>(labels);
    supcon_gemm<<<dim3(NBLK, SPLITS), 256, 98304>>>();
    finalize_rows<<<N_TOT / 8, 256>>>(labels);
    reduce_kernel<<<1, 256>>>((float*)d_out);
}

// round 9
// speedup vs baseline: 2.1427x; 1.3534x over previous
#include <cuda_runtime.h>
#include <cuda_bf16.h>
#include <cstdint>

// ============================================================================
// SupCon loss, fused + symmetric. S = Xn Xn^T / T is symmetric: only upper-
// triangular 128x128 tiles computed (2080 of 4096). Off-diag tile (bi,jb)
// contributes exp row-sums to block bi (slot jb) and exp col-sums (= row-sums
// of block jb by symmetry) to slot bi. Cross-warp partials are combined in
// smem (deterministically) before the single global write per (slot,row).
// Positives via label buckets (p~1/1000). out = sum_i loss_i.
// ============================================================================

#define N_TOT   8192
#define D_DIM   128
#define NBLK    64
#define NTILES  (NBLK * (NBLK + 1) / 2)   /* 2080 */
#define KEXP    14.426950408889634f       /* 10*log2(e) */

__device__ __align__(16) __nv_bfloat16 g_x[N_TOT * D_DIM];
__device__ float g_seb[NBLK][N_TOT];      // slot s = co-block id
__device__ float g_loss[N_TOT];
__device__ int   g_is32;
__device__ int   g_part[32][1024];
__device__ int   g_start[1025];
__device__ int   g_items[N_TOT];

// ---------------------------------------------------------------- helpers
__device__ __forceinline__ uint32_t smem_to_u32(const void* p) {
    uint32_t a;
    asm("{ .reg .u64 t; cvta.to.shared.u64 t, %1; cvt.u32.u64 %0, t; }"
        : "=r"(a) : "l"(p));
    return a;
}
__device__ __forceinline__ void ldsm_x4(uint32_t& r0, uint32_t& r1,
                                        uint32_t& r2, uint32_t& r3,
                                        uint32_t addr) {
    asm volatile("ldmatrix.sync.aligned.m8n8.x4.shared.b16 {%0,%1,%2,%3}, [%4];"
                 : "=r"(r0), "=r"(r1), "=r"(r2), "=r"(r3) : "r"(addr));
}
__device__ __forceinline__ void mma_16816(float& c0, float& c1, float& c2, float& c3,
                                          uint32_t a0, uint32_t a1, uint32_t a2, uint32_t a3,
                                          uint32_t b0, uint32_t b1) {
    asm volatile(
        "mma.sync.aligned.m16n8k16.row.col.f32.bf16.bf16.f32 "
        "{%0,%1,%2,%3}, {%4,%5,%6,%7}, {%8,%9}, {%0,%1,%2,%3};"
        : "+f"(c0), "+f"(c1), "+f"(c2), "+f"(c3)
        : "r"(a0), "r"(a1), "r"(a2), "r"(a3), "r"(b0), "r"(b1));
}
__device__ __forceinline__ int getlab(const long long* L64, int is32, int i) {
    return is32 ? ((const int*)L64)[i] : (int)L64[i];
}
#define CP_ASYNC16(dst, src) \
    asm volatile("cp.async.cg.shared.global [%0], [%1], 16;" \
                 :: "r"(dst), "l"(src) : "memory")
#define CP_COMMIT() asm volatile("cp.async.commit_group;" ::: "memory")
#define CP_WAIT0()  asm volatile("cp.async.wait_group 0;" ::: "memory")

// ---------------------------------------------------------------- kernel 1
__global__ void norm_kernel(const float* __restrict__ emb) {
    int row  = blockIdx.x * 8 + (threadIdx.x >> 5);
    int lane = threadIdx.x & 31;
    const float4* e4 = (const float4*)(emb + (size_t)row * D_DIM);
    float4 v = e4[lane];
    float ss = v.x * v.x + v.y * v.y + v.z * v.z + v.w * v.w;
    #pragma unroll
    for (int m = 16; m; m >>= 1) ss += __shfl_xor_sync(0xffffffffu, ss, m);
    float inv = 1.0f / fmaxf(sqrtf(ss), 1e-12f);
    __nv_bfloat162* o = (__nv_bfloat162*)(g_x + (size_t)row * D_DIM);
    o[lane * 2]     = __floats2bfloat162_rn(v.x * inv, v.y * inv);
    o[lane * 2 + 1] = __floats2bfloat162_rn(v.z * inv, v.w * inv);
}

// ---------------------------------------------------------------- bucket build
__global__ void hist1(const long long* __restrict__ lab64) {
    __shared__ int cnt[1024];
    __shared__ int s_is32;
    int tid = threadIdx.x, blk = blockIdx.x;
    if (tid == 0) s_is32 = 0;
    #pragma unroll
    for (int j = 0; j < 4; j++) cnt[tid + j * 256] = 0;
    __syncthreads();
    if (tid < 64) {
        unsigned hi = (unsigned)(((unsigned long long)lab64[tid]) >> 32);
        if (hi != 0u) atomicOr(&s_is32, 1);
    }
    __syncthreads();
    int is32 = s_is32;
    if (tid == 0 && blk == 0) g_is32 = is32;
    int lab = getlab(lab64, is32, blk * 256 + tid);
    atomicAdd(&cnt[lab], 1);
    __syncthreads();
    #pragma unroll
    for (int j = 0; j < 4; j++) g_part[blk][tid + j * 256] = cnt[tid + j * 256];
}

__global__ void hist2() {
    __shared__ int wsum[32];
    int tid = threadIdx.x;
    int l = tid & 31, w = tid >> 5;
    int pref[32];
    int run = 0;
    #pragma unroll
    for (int c = 0; c < 32; c++) {
        int t = g_part[c][tid];
        pref[c] = run;
        run += t;
    }
    int x = run;
    #pragma unroll
    for (int o = 1; o < 32; o <<= 1) {
        int v = __shfl_up_sync(0xffffffffu, x, o);
        if (l >= o) x += v;
    }
    if (l == 31) wsum[w] = x;
    __syncthreads();
    if (tid < 32) {
        int y = wsum[tid];
        #pragma unroll
        for (int o = 1; o < 32; o <<= 1) {
            int v = __shfl_up_sync(0xffffffffu, y, o);
            if (tid >= o) y += v;
        }
        wsum[tid] = y;
    }
    __syncthreads();
    int incl = x + (w ? wsum[w - 1] : 0);
    int excl = incl - run;
    g_start[tid] = excl;
    if (tid == 0) g_start[1024] = N_TOT;
    #pragma unroll
    for (int c = 0; c < 32; c++) g_part[c][tid] = pref[c] + excl;
}

__global__ void hist3(const long long* __restrict__ lab64) {
    __shared__ int cnt[1024];
    int tid = threadIdx.x, blk = blockIdx.x;
    int l = tid & 31, w = tid >> 5;
    #pragma unroll
    for (int j = 0; j < 4; j++) cnt[tid + j * 256] = 0;
    int row = blk * 256 + tid;
    int lab = getlab(lab64, g_is32, row);
    unsigned mask = __match_any_sync(0xffffffffu, lab);
    int rank_w = __popc(mask & ((1u << l) - 1u));
    int cnt_w  = __popc(mask);
    __syncthreads();
    int base = 0;
    #pragma unroll
    for (int w2 = 0; w2 < 8; w2++) {
        if (w == w2) {
            base = cnt[lab];
            __syncwarp();
            if (rank_w == 0) cnt[lab] = base + cnt_w;
        }
        __syncthreads();
    }
    g_items[g_part[blk][lab] + base + rank_w] = row;
}

// ---------------------------------------------------------------- kernel 2:
// symmetric GEMM + exp row/col sums. 2080 CTAs, 256 thr (4x2 warp grid).
// smem: [0,32K) A, [32K,64K) B, [64K,+1K) sRow[2][128], [+1K,+3K) sCol[4][128]
__global__ void __launch_bounds__(256, 2) supcon_gemm() {
    extern __shared__ char smem[];
    uint32_t a_sm = smem_to_u32(smem);
    uint32_t b_sm = a_sm + 32768;
    float* sRow = (float*)(smem + 65536);          // [2][128]
    float* sCol = (float*)(smem + 65536 + 1024);   // [4][128]

    // triangular decode: blockIdx.x -> (bi, jb), jb >= bi
    int u = blockIdx.x, bi = 0;
    while (u >= NBLK - bi) { u -= NBLK - bi; bi++; }
    int jb = bi + u;
    bool diag = (jb == bi);

    int tid = threadIdx.x;
    int w   = tid >> 5;
    int l   = tid & 31;
    int wy  = w >> 1;
    int wx  = w & 1;
    int qp  = l & 3;

    // load A (and B unless diagonal); swizzle: 16B chunk c of row r -> c^(r&7)
    {
        const char* src = (const char*)g_x + (size_t)bi * 32768;
        #pragma unroll
        for (int j = 0; j < 8; j++) {
            int it = tid + j * 256;
            int r = it >> 4, c = it & 15;
            CP_ASYNC16(a_sm + r * 256 + ((c ^ (r & 7)) << 4),
                       src + (size_t)it * 16);
        }
    }
    if (!diag) {
        const char* src = (const char*)g_x + (size_t)jb * 32768;
        #pragma unroll
        for (int j = 0; j < 8; j++) {
            int it = tid + j * 256;
            int r = it >> 4, c = it & 15;
            CP_ASYNC16(b_sm + r * 256 + ((c ^ (r & 7)) << 4),
                       src + (size_t)it * 16);
        }
    }
    CP_COMMIT();

    int a_row  = 32 * wy + ((l >> 3) & 1) * 8 + (l & 7);
    int a_csel = (l >> 4) & 1;
    int a_rx   = a_row & 7;
    int b_row  = 64 * wx + ((l >> 4) & 1) * 8 + (l & 7);
    int b_csel = (l >> 3) & 1;
    int b_rx   = b_row & 7;

    uint32_t a_base0 = a_sm + a_row * 256;
    uint32_t b_base0 = (diag ? a_sm : b_sm) + b_row * 256;

    CP_WAIT0();
    __syncthreads();

    float acc[2][8][4];
    #pragma unroll
    for (int m = 0; m < 2; m++)
        #pragma unroll
        for (int n = 0; n < 8; n++)
            #pragma unroll
            for (int e = 0; e < 4; e++) acc[m][n][e] = 0.f;

    #pragma unroll
    for (int k = 0; k < 8; k++) {
        uint32_t ka = (uint32_t)(((2 * k + a_csel) ^ a_rx) << 4);
        uint32_t kb = (uint32_t)(((2 * k + b_csel) ^ b_rx) << 4);
        uint32_t a0[4], a1[4];
        ldsm_x4(a0[0], a0[1], a0[2], a0[3], a_base0 + ka);
        ldsm_x4(a1[0], a1[1], a1[2], a1[3], a_base0 + 4096 + ka);
        #pragma unroll
        for (int g = 0; g < 4; g++) {
            uint32_t b0, b1, b2, b3;
            ldsm_x4(b0, b1, b2, b3, b_base0 + g * 4096 + kb);
            mma_16816(acc[0][2*g][0],   acc[0][2*g][1],   acc[0][2*g][2],   acc[0][2*g][3],
                      a0[0], a0[1], a0[2], a0[3], b0, b1);
            mma_16816(acc[0][2*g+1][0], acc[0][2*g+1][1], acc[0][2*g+1][2], acc[0][2*g+1][3],
                      a0[0], a0[1], a0[2], a0[3], b2, b3);
            mma_16816(acc[1][2*g][0],   acc[1][2*g][1],   acc[1][2*g][2],   acc[1][2*g][3],
                      a1[0], a1[1], a1[2], a1[3], b0, b1);
            mma_16816(acc[1][2*g+1][0], acc[1][2*g+1][1], acc[1][2*g+1][2], acc[1][2*g+1][3],
                      a1[0], a1[1], a1[2], a1[3], b2, b3);
        }
    }

    // ---- epilogue: exp once per element; warp-partial row + col sums ----
    float rowse[4] = {0.f, 0.f, 0.f, 0.f};     // [2m+h]
    float colse[16];
    #pragma unroll
    for (int c = 0; c < 16; c++) colse[c] = 0.f;

    #pragma unroll
    for (int m = 0; m < 2; m++)
        #pragma unroll
        for (int n = 0; n < 8; n++) {
            float ex0 = exp2f(fmaf(acc[m][n][0], KEXP, -KEXP));
            float ex1 = exp2f(fmaf(acc[m][n][1], KEXP, -KEXP));
            float ex2 = exp2f(fmaf(acc[m][n][2], KEXP, -KEXP));
            float ex3 = exp2f(fmaf(acc[m][n][3], KEXP, -KEXP));
            rowse[2*m]     += ex0 + ex1;
            rowse[2*m + 1] += ex2 + ex3;
            colse[2*n]     += ex0 + ex2;
            colse[2*n + 1] += ex1 + ex3;
        }

    // warp-level reduce, deposit per-warp partials in smem (disjoint slots)
    #pragma unroll
    for (int v = 0; v < 4; v++) {
        #pragma unroll
        for (int off = 1; off <= 2; off <<= 1)
            rowse[v] += __shfl_xor_sync(0xffffffffu, rowse[v], off);
    }
    if (qp == 0) {
        int q = l >> 2;
        #pragma unroll
        for (int m = 0; m < 2; m++)
            #pragma unroll
            for (int h = 0; h < 2; h++) {
                int row_l = 32 * wy + 16 * m + 8 * h + q;
                sRow[wx * 128 + row_l] = rowse[2*m + h];   // warp covers 64 cols
            }
    }
    #pragma unroll
    for (int c = 0; c < 16; c++) {
        #pragma unroll
        for (int off = 4; off <= 16; off <<= 1)
            colse[c] += __shfl_xor_sync(0xffffffffu, colse[c], off);
    }
    if (l < 4) {
        #pragma unroll
        for (int n = 0; n < 8; n++)
            #pragma unroll
            for (int e = 0; e < 2; e++) {
                int col_l = 64 * wx + 16 * (n >> 1) + 8 * (n & 1) + l * 2 + e;
                sCol[wy * 128 + col_l] = colse[2*n + e];   // warp covers 32 rows
            }
    }
    __syncthreads();

    // fixed-order combine + single global write per (slot,row): deterministic
    if (tid < 128) {
        g_seb[jb][bi * 128 + tid] = sRow[tid] + sRow[128 + tid];
    } else if (!diag) {
        int c = tid - 128;
        g_seb[bi][jb * 128 + c] = (sCol[c] + sCol[128 + c])
                                + (sCol[256 + c] + sCol[384 + c]);
    }
}

// ---------------------------------------------------------------- kernel 3:
// warp per row: se assemble (64 slots), d_ii, sparse pd/cf from bucket.
__global__ void finalize_rows(const long long* __restrict__ lab64) {
    int i = (blockIdx.x * blockDim.x + threadIdx.x) >> 5;
    int l = threadIdx.x & 31;

    const uint2* xr = (const uint2*)(g_x + (size_t)i * D_DIM);
    uint2 xv = xr[l];
    __nv_bfloat162 p0 = *(__nv_bfloat162*)&xv.x;
    __nv_bfloat162 p1 = *(__nv_bfloat162*)&xv.y;
    float x0 = __bfloat162float(p0.x), x1 = __bfloat162float(p0.y);
    float x2 = __bfloat162float(p1.x), x3 = __bfloat162float(p1.y);

    float dii = x0 * x0 + x1 * x1 + x2 * x2 + x3 * x3;
    #pragma unroll
    for (int m = 16; m; m >>= 1) dii += __shfl_xor_sync(0xffffffffu, dii, m);

    float se = g_seb[l][i] + g_seb[l + 32][i];
    #pragma unroll
    for (int m = 16; m; m >>= 1) se += __shfl_xor_sync(0xffffffffu, se, m);
    se -= exp2f(fmaf(dii, KEXP, -KEXP));

    int lab = getlab(lab64, g_is32, i);
    int s = g_start[lab], e = g_start[lab + 1];
    float pd = 0.f;
    for (int m = s; m < e; m++) {
        int j = g_items[m];
        if (j == i) continue;
        uint2 yv = ((const uint2*)(g_x + (size_t)j * D_DIM))[l];
        __nv_bfloat162 q0 = *(__nv_bfloat162*)&yv.x;
        __nv_bfloat162 q1 = *(__nv_bfloat162*)&yv.y;
        float d = x0 * __bfloat162float(q0.x) + x1 * __bfloat162float(q0.y)
                + x2 * __bfloat162float(q1.x) + x3 * __bfloat162float(q1.y);
        #pragma unroll
        for (int m2 = 16; m2; m2 >>= 1) d += __shfl_xor_sync(0xffffffffu, d, m2);
        pd += d;
    }
    if (l == 0) {
        float cf  = (float)(e - s - 1);
        float lse = 10.0f + logf(se);
        g_loss[i] = -(10.0f * pd - cf * lse) / (cf + 1.17549435e-38f);
    }
}

// ---------------------------------------------------------------- kernel 4
__global__ void reduce_kernel(float* out) {
    __shared__ float sh[256];
    float a = 0.f;
    for (int k = threadIdx.x; k < N_TOT; k += 256) a += g_loss[k];
    sh[threadIdx.x] = a;
    __syncthreads();
    #pragma unroll
    for (int s = 128; s; s >>= 1) {
        if (threadIdx.x < s) sh[threadIdx.x] += sh[threadIdx.x + s];
        __syncthreads();
    }
    if (threadIdx.x == 0) out[0] = sh[0];
}

// ---------------------------------------------------------------- launch
extern "C" void kernel_launch(void* const* d_in, const int* in_sizes, int n_in,
                              void* d_out, int out_size) {
    const float*     emb    = (const float*)d_in[0];
    const long long* labels = (const long long*)d_in[1];

    cudaFuncSetAttribute(supcon_gemm, cudaFuncAttributeMaxDynamicSharedMemorySize, 68608);

    norm_kernel<<<N_TOT / 8, 256>>>(emb);
    hist1<<<32, 256>>>(labels);
    hist2<<<1, 1024>>>();
    hist3<<<32, 256>>>(labels);
    supcon_gemm<<<NTILES, 256, 68608>>>();
    finalize_rows<<<N_TOT / 8, 256>>>(labels);
    reduce_kernel<<<1, 256>>>((float*)d_out);
}